// round 6
// baseline (speedup 1.0000x reference)
#include <cuda_runtime.h>
#include <cuda_bf16.h>
#include <math.h>
#include <math_constants.h>
#include <cstdint>

#define BB 2
#define SS 2048
#define DD 1024
#define HH 16
#define DK 64

// ---------------- scratch (allocation-free: __device__ globals) ----------------
__device__ float g_qbuf[BB*HH*SS*DK];
__device__ float g_kbuf[BB*HH*SS*DK];
__device__ float g_vbuf[BB*HH*SS*DK];
__device__ float g_ct[BB*SS*32];
__device__ float g_st[BB*SS*32];
__device__ __nv_bfloat16 g_xhi[BB*SS*DD], g_xlo[BB*SS*DD];
__device__ __nv_bfloat16 g_wchi[3*DD*DD], g_wclo[3*DD*DD];   // Wq|Wk|Wv concat
__device__ __nv_bfloat16 g_wohi[DD*DD],  g_wolo[DD*DD];
__device__ __nv_bfloat16 g_abhi[BB*SS*DD], g_ablo[BB*SS*DD];

// ======================= helpers ================================================
__device__ __forceinline__ uint32_t smem_u32(const void* p) {
    uint32_t a;
    asm("{ .reg .u64 t; cvta.to.shared.u64 t, %1; cvt.u32.u64 %0, t; }" : "=r"(a) : "l"(p));
    return a;
}
__device__ __forceinline__ uint32_t pack_bf16(float a, float b) {
    __nv_bfloat16 ha = __float2bfloat16_rn(a);
    __nv_bfloat16 hb = __float2bfloat16_rn(b);
    return (uint32_t)__bfloat16_as_ushort(ha) | ((uint32_t)__bfloat16_as_ushort(hb) << 16);
}
__device__ __forceinline__ void mma_bf16(float c[4], const uint32_t a[4],
                                         uint32_t b0, uint32_t b1) {
    asm volatile(
        "mma.sync.aligned.m16n8k16.row.col.f32.bf16.bf16.f32 "
        "{%0,%1,%2,%3},{%4,%5,%6,%7},{%8,%9},{%0,%1,%2,%3};"
        : "+f"(c[0]), "+f"(c[1]), "+f"(c[2]), "+f"(c[3])
        : "r"(a[0]), "r"(a[1]), "r"(a[2]), "r"(a[3]), "r"(b0), "r"(b1));
}
__device__ __forceinline__ void store_hilo(uint32_t* hiArr, uint32_t* loArr,
                                           int base, float4 v) {
    float hx = __bfloat162float(__float2bfloat16_rn(v.x));
    float hy = __bfloat162float(__float2bfloat16_rn(v.y));
    float hz = __bfloat162float(__float2bfloat16_rn(v.z));
    float hw = __bfloat162float(__float2bfloat16_rn(v.w));
    uint2 hi = make_uint2(pack_bf16(hx, hy), pack_bf16(hz, hw));
    uint2 lo = make_uint2(pack_bf16(v.x - hx, v.y - hy), pack_bf16(v.z - hz, v.w - hw));
    *(uint2*)&hiArr[base] = hi;
    *(uint2*)&loArr[base] = lo;
}
__device__ __forceinline__ float exp2a(float x) {
    x = fmaxf(x, -126.0f);
    float z = x + 12582912.0f;
    uint32_t iz = __float_as_uint(z);
    float f = x - (z - 12582912.0f);
    float p = 0.0013333558f;
    p = fmaf(p, f, 0.0096180885f);
    p = fmaf(p, f, 0.0555041087f);
    p = fmaf(p, f, 0.2402265069f);
    p = fmaf(p, f, 0.6931471806f);
    p = fmaf(p, f, 1.0f);
    return __uint_as_float(__float_as_uint(p) + (iz << 23));
}
__device__ __forceinline__ void cp16(uint32_t dst, const void* src) {
    asm volatile("cp.async.ca.shared.global [%0], [%1], 16;" :: "r"(dst), "l"(src));
}

// ======================= fused pre-pass: all f32 -> bf16 hi/lo ==================
#define NX4 (BB*SS*DD/4)
#define NW4 (DD*DD/4)
__global__ void cvt_all_kernel(const float* __restrict__ x,  const float* __restrict__ Wq,
                               const float* __restrict__ Wk, const float* __restrict__ Wv,
                               const float* __restrict__ Wo,
                               __nv_bfloat16* __restrict__ xhi, __nv_bfloat16* __restrict__ xlo,
                               __nv_bfloat16* __restrict__ wchi, __nv_bfloat16* __restrict__ wclo,
                               __nv_bfloat16* __restrict__ wohi, __nv_bfloat16* __restrict__ wolo)
{
    int idx = blockIdx.x * blockDim.x + threadIdx.x;
    const float* src;
    __nv_bfloat16 *hi, *lo;
    int off;
    if (idx < NX4) {
        src = x; hi = xhi; lo = xlo; off = idx;
    } else if (idx < NX4 + NW4) {
        src = Wq; hi = wchi; lo = wclo; off = idx - NX4;
    } else if (idx < NX4 + 2*NW4) {
        src = Wk; hi = wchi + DD*DD; lo = wclo + DD*DD; off = idx - NX4 - NW4;
    } else if (idx < NX4 + 3*NW4) {
        src = Wv; hi = wchi + 2*DD*DD; lo = wclo + 2*DD*DD; off = idx - NX4 - 2*NW4;
    } else if (idx < NX4 + 4*NW4) {
        src = Wo; hi = wohi; lo = wolo; off = idx - NX4 - 3*NW4;
    } else return;
    float4 v = *(const float4*)&src[(size_t)off * 4];
    float hx = __bfloat162float(__float2bfloat16_rn(v.x));
    float hy = __bfloat162float(__float2bfloat16_rn(v.y));
    float hz = __bfloat162float(__float2bfloat16_rn(v.z));
    float hw = __bfloat162float(__float2bfloat16_rn(v.w));
    *(uint2*)&hi[(size_t)off * 4] = make_uint2(pack_bf16(hx, hy), pack_bf16(hz, hw));
    *(uint2*)&lo[(size_t)off * 4] = make_uint2(pack_bf16(v.x - hx, v.y - hy),
                                               pack_bf16(v.z - hz, v.w - hw));
}

// ======================= RoPE table =============================================
__global__ void rope_tab_kernel(const int* __restrict__ tp, float* __restrict__ ct,
                                float* __restrict__ st)
{
    int idx = blockIdx.x * blockDim.x + threadIdx.x;
    if (idx >= BB*SS*32) return;
    int m = idx >> 5;
    int p = idx & 31;
    float inv = powf(10000.0f, -(float)(2*p) * (1.0f/64.0f));
    float freq = (float)tp[m] * inv;
    float sn, cs;
    sincosf(freq, &sn, &cs);
    ct[idx] = cs;
    st[idx] = sn;
}

// ======================= GEMM v3: 512 threads, 16 warps, fused QKV ==============
// mode 3: B = wcat [3072,1024]; seg from blockIdx.x>>3 -> Q(rope)/K(rope)/V
// mode 2: plain output (Wo)
#define SROW 20
#define G2_ARR 2560                    // 128*SROW uint32
#define G2_STAGE (4*G2_ARR)
#define G2_SMEM_BYTES (2*G2_STAGE*4)   // 81920 B

__global__ __launch_bounds__(512, 1)
void gemm_mma3_kernel(const __nv_bfloat16* __restrict__ Ahi, const __nv_bfloat16* __restrict__ Alo,
                      const __nv_bfloat16* __restrict__ Bh,  const __nv_bfloat16* __restrict__ Bl,
                      const float* __restrict__ ct, const float* __restrict__ st,
                      float* __restrict__ outq, float* __restrict__ outk,
                      float* __restrict__ outv, float* __restrict__ outp, int mode)
{
    extern __shared__ uint32_t su2[];
    const uint32_t sbase = smem_u32(su2);

    const int tid = threadIdx.x;
    const int wid = tid >> 5;
    const int lid = tid & 31;
    const int wm = wid >> 2;          // 0..3
    const int wn = wid & 3;           // 0..3
    const int r  = lid >> 2;
    const int c4 = lid & 3;
    const int m0 = blockIdx.y * 128;

    int n0, md;
    const __nv_bfloat16 *bhp = Bh, *blp = Bl;
    float* outsel;
    if (mode == 3) {
        int seg = blockIdx.x >> 3;
        n0 = (blockIdx.x & 7) * 128;
        bhp += (size_t)seg * DD * DD;
        blp += (size_t)seg * DD * DD;
        outsel = (seg == 0) ? outq : ((seg == 1) ? outk : outv);
        md = (seg < 2) ? 0 : 1;
    } else {
        n0 = blockIdx.x * 128;
        outsel = outp;
        md = 2;
    }

    const int prow = tid >> 2;        // 0..127
    const int pch  = tid & 3;

    float C[2][4][4];
    #pragma unroll
    for (int mt = 0; mt < 2; mt++)
        #pragma unroll
        for (int nt = 0; nt < 4; nt++)
            #pragma unroll
            for (int q = 0; q < 4; q++) C[mt][nt][q] = 0.f;

    auto prefetch = [&](int kt, int st2) {
        const int k0 = kt * 32;
        uint32_t d = sbase + (uint32_t)(st2 * G2_STAGE + prow * SROW + pch * 4) * 4u;
        size_t goA = (size_t)(m0 + prow) * DD + k0 + pch * 8;
        size_t goB = (size_t)(n0 + prow) * DD + k0 + pch * 8;
        cp16(d,                Ahi + goA);
        cp16(d + G2_ARR * 4u,  Alo + goA);
        cp16(d + 2u*G2_ARR*4u, bhp + goB);
        cp16(d + 3u*G2_ARR*4u, blp + goB);
        asm volatile("cp.async.commit_group;" ::: "memory");
    };

    prefetch(0, 0);

    const int aoff = (wm * 32 + r) * SROW + c4;
    const int boff = (wn * 32 + r) * SROW + c4;

    for (int kt = 0; kt < 32; kt++) {
        asm volatile("cp.async.wait_group 0;" ::: "memory");
        __syncthreads();
        if (kt < 31) prefetch(kt + 1, (kt + 1) & 1);

        uint32_t* sAhi = su2 + (kt & 1) * G2_STAGE;
        uint32_t* sAlo = sAhi + G2_ARR;
        uint32_t* sBhi = sAlo + G2_ARR;
        uint32_t* sBlo = sBhi + G2_ARR;

        #pragma unroll
        for (int kc = 0; kc < 2; kc++) {
            uint32_t bh[4][2], bl[4][2];
            #pragma unroll
            for (int nt = 0; nt < 4; nt++) {
                int bb = boff + nt * 8 * SROW + kc * 8;
                bh[nt][0] = sBhi[bb];     bh[nt][1] = sBhi[bb + 4];
                bl[nt][0] = sBlo[bb];     bl[nt][1] = sBlo[bb + 4];
            }
            #pragma unroll
            for (int mt = 0; mt < 2; mt++) {
                int ab = aoff + mt * 16 * SROW + kc * 8;
                uint32_t ah[4], al[4];
                ah[0] = sAhi[ab];             ah[1] = sAhi[ab + 8 * SROW];
                ah[2] = sAhi[ab + 4];         ah[3] = sAhi[ab + 8 * SROW + 4];
                al[0] = sAlo[ab];             al[1] = sAlo[ab + 8 * SROW];
                al[2] = sAlo[ab + 4];         al[3] = sAlo[ab + 8 * SROW + 4];
                #pragma unroll
                for (int nt = 0; nt < 4; nt++) {
                    mma_bf16(C[mt][nt], ah, bh[nt][0], bh[nt][1]);
                    mma_bf16(C[mt][nt], ah, bl[nt][0], bl[nt][1]);
                    mma_bf16(C[mt][nt], al, bh[nt][0], bh[nt][1]);
                }
            }
        }
    }

    // ---------------- epilogue ----------------
    #pragma unroll
    for (int mt = 0; mt < 2; mt++) {
        const int row0 = m0 + wm * 32 + mt * 16 + r;
        const int row1 = row0 + 8;
        #pragma unroll
        for (int nt = 0; nt < 4; nt++) {
            const int ncol = n0 + wn * 32 + nt * 8 + c4 * 2;
            float v00 = C[mt][nt][0], v01 = C[mt][nt][1];
            float v10 = C[mt][nt][2], v11 = C[mt][nt][3];
            if (md == 2) {
                *(float2*)&outsel[(size_t)row0 * DD + ncol] = make_float2(v00, v01);
                *(float2*)&outsel[(size_t)row1 * DD + ncol] = make_float2(v10, v11);
            } else {
                const int h   = ncol >> 6;
                const int dk0 = ncol & 63;
                if (md == 0) {
                    const int p = dk0 >> 1;
                    float cs0 = ct[(size_t)row0 * 32 + p], sn0 = st[(size_t)row0 * 32 + p];
                    float cs1 = ct[(size_t)row1 * 32 + p], sn1 = st[(size_t)row1 * 32 + p];
                    float t00 = cs0 * v00 - sn0 * v01;
                    float t01 = sn0 * v00 + cs0 * v01;
                    float t10 = cs1 * v10 - sn1 * v11;
                    float t11 = sn1 * v10 + cs1 * v11;
                    v00 = t00; v01 = t01; v10 = t10; v11 = t11;
                }
                const int b0r = row0 >> 11, s0 = row0 & (SS - 1);
                const int b1r = row1 >> 11, s1 = row1 & (SS - 1);
                *(float2*)&outsel[((size_t)(b0r * HH + h) * SS + s0) * DK + dk0] =
                    make_float2(v00, v01);
                *(float2*)&outsel[((size_t)(b1r * HH + h) * SS + s1) * DK + dk0] =
                    make_float2(v10, v11);
            }
        }
    }
}

// ======================= mma.sync flash attention (round-5, unchanged) =========
#define QST 36
#define VST 68
#define UQH 0
#define UQL (UQH + 128*QST)
#define UKH (UQL + 128*QST)
#define UKL (UKH + 128*QST)
#define UVH (UKL + 128*QST)
#define UVL (UVH + 64*VST)
#define UPH (UVL + 64*VST)
#define UPL (UPH + 128*VST)
#define ATTN_SMEM_U32 (UPL + 128*VST)
#define ATTN_SMEM_BYTES (ATTN_SMEM_U32 * 4)

__global__ __launch_bounds__(256)
void attn_mma_kernel(const float* __restrict__ qb, const float* __restrict__ kb,
                     const float* __restrict__ vb,
                     __nv_bfloat16* __restrict__ ohi, __nv_bfloat16* __restrict__ olo)
{
    extern __shared__ uint32_t su[];
    uint32_t* sQh = su + UQH;
    uint32_t* sQl = su + UQL;
    uint32_t* sKh = su + UKH;
    uint32_t* sKl = su + UKL;
    uint32_t* sVh = su + UVH;
    uint32_t* sVl = su + UVL;
    uint32_t* sPh = su + UPH;
    uint32_t* sPl = su + UPL;

    const int tid = threadIdx.x;
    const int wid = tid >> 5;
    const int lid = tid & 31;
    const int r   = lid >> 2;
    const int c4  = lid & 3;
    const int bh  = blockIdx.y;
    const int qt  = gridDim.x - 1 - blockIdx.x;
    const int q0  = qt * 128;

    const float* qh = qb + (size_t)bh * SS * DK;
    const float* kh = kb + (size_t)bh * SS * DK;
    const float* vh = vb + (size_t)bh * SS * DK;

    const float CSC = 0.125f * 1.44269504088896f;
    #pragma unroll
    for (int it = 0; it < 8; it++) {
        int idx = tid + it * 256;
        int row = idx >> 4, ch = idx & 15;
        float4 v = *(const float4*)&qh[(size_t)(q0 + row) * DK + ch * 4];
        v.x *= CSC; v.y *= CSC; v.z *= CSC; v.w *= CSC;
        store_hilo(sQh, sQl, row * QST + ch * 2, v);
    }

    float mrow[2] = {-CUDART_INF_F, -CUDART_INF_F};
    float lrow[2] = {0.f, 0.f};
    float O[8][4];
    #pragma unroll
    for (int i = 0; i < 8; i++)
        #pragma unroll
        for (int j = 0; j < 4; j++) O[i][j] = 0.f;

    const int abase = (wid * 16 + r) * QST + c4;
    const int pbase = (wid * 16 + r) * VST + c4;
    const int cpr  = tid & 63;
    const int dgrp = tid >> 6;

    for (int kt = 0; kt <= qt; kt++) {
        const int k0 = kt * 128;
        __syncthreads();

        #pragma unroll
        for (int it = 0; it < 8; it++) {
            int idx = tid + it * 256;
            int row = idx >> 4, ch = idx & 15;
            float4 v = *(const float4*)&kh[(size_t)(k0 + row) * DK + ch * 4];
            store_hilo(sKh, sKl, row * QST + ch * 2, v);
        }
        #pragma unroll
        for (int dd = 0; dd < 4; dd++) {
            int d = dgrp * 16 + dd * 4;
            float4 v0 = *(const float4*)&vh[(size_t)(k0 + 2*cpr)     * DK + d];
            float4 v1 = *(const float4*)&vh[(size_t)(k0 + 2*cpr + 1) * DK + d];
            float a0[4] = {v0.x, v0.y, v0.z, v0.w};
            float a1[4] = {v1.x, v1.y, v1.z, v1.w};
            #pragma unroll
            for (int e = 0; e < 4; e++) {
                float h0 = __bfloat162float(__float2bfloat16_rn(a0[e]));
                float h1 = __bfloat162float(__float2bfloat16_rn(a1[e]));
                sVh[(d + e) * VST + cpr] = pack_bf16(h0, h1);
                sVl[(d + e) * VST + cpr] = pack_bf16(a0[e] - h0, a1[e] - h1);
            }
        }
        __syncthreads();

        float Sv[16][4];
        #pragma unroll
        for (int nt = 0; nt < 16; nt++)
            #pragma unroll
            for (int q = 0; q < 4; q++) Sv[nt][q] = 0.f;

        #pragma unroll
        for (int kc = 0; kc < 4; kc++) {
            int ao = abase + kc * 8;
            uint32_t ah[4], al[4];
            ah[0] = sQh[ao];              ah[1] = sQh[ao + 8*QST];
            ah[2] = sQh[ao + 4];          ah[3] = sQh[ao + 8*QST + 4];
            al[0] = sQl[ao];              al[1] = sQl[ao + 8*QST];
            al[2] = sQl[ao + 4];          al[3] = sQl[ao + 8*QST + 4];
            #pragma unroll
            for (int nt = 0; nt < 16; nt++) {
                int bo = (nt * 8 + r) * QST + kc * 8 + c4;
                uint32_t bh0 = sKh[bo], bh1 = sKh[bo + 4];
                uint32_t bl0 = sKl[bo], bl1 = sKl[bo + 4];
                mma_bf16(Sv[nt], ah, bh0, bh1);
                mma_bf16(Sv[nt], ah, bl0, bl1);
                mma_bf16(Sv[nt], al, bh0, bh1);
            }
        }

        if (kt == qt) {
            int row0 = wid * 16 + r;
            int row1 = row0 + 8;
            #pragma unroll
            for (int nt = 0; nt < 16; nt++) {
                int col = nt * 8 + c4 * 2;
                if (col     > row0) Sv[nt][0] = -1e30f;
                if (col + 1 > row0) Sv[nt][1] = -1e30f;
                if (col     > row1) Sv[nt][2] = -1e30f;
                if (col + 1 > row1) Sv[nt][3] = -1e30f;
            }
        }

        #pragma unroll
        for (int hrow = 0; hrow < 2; hrow++) {
            float tm = -CUDART_INF_F;
            #pragma unroll
            for (int nt = 0; nt < 16; nt++) {
                tm = fmaxf(tm, Sv[nt][2*hrow]);
                tm = fmaxf(tm, Sv[nt][2*hrow + 1]);
            }
            tm = fmaxf(tm, __shfl_xor_sync(0xffffffffu, tm, 1));
            tm = fmaxf(tm, __shfl_xor_sync(0xffffffffu, tm, 2));
            float mn = fmaxf(mrow[hrow], tm);
            float alpha = exp2a(mrow[hrow] - mn);
            float ps = 0.f;
            #pragma unroll
            for (int nt = 0; nt < 16; nt++) {
                float p0 = exp2a(Sv[nt][2*hrow]     - mn);
                float p1 = exp2a(Sv[nt][2*hrow + 1] - mn);
                Sv[nt][2*hrow]     = p0;
                Sv[nt][2*hrow + 1] = p1;
                ps += p0 + p1;
            }
            ps += __shfl_xor_sync(0xffffffffu, ps, 1);
            ps += __shfl_xor_sync(0xffffffffu, ps, 2);
            lrow[hrow] = lrow[hrow] * alpha + ps;
            mrow[hrow] = mn;
            #pragma unroll
            for (int nt2 = 0; nt2 < 8; nt2++) {
                O[nt2][2*hrow]     *= alpha;
                O[nt2][2*hrow + 1] *= alpha;
            }
        }

        #pragma unroll
        for (int nt = 0; nt < 16; nt++) {
            int w0 = (wid * 16 + r) * VST + nt * 4 + c4;
            float p0 = Sv[nt][0], p1 = Sv[nt][1];
            float h0 = __bfloat162float(__float2bfloat16_rn(p0));
            float h1 = __bfloat162float(__float2bfloat16_rn(p1));
            sPh[w0] = pack_bf16(h0, h1);
            sPl[w0] = pack_bf16(p0 - h0, p1 - h1);
            float p2 = Sv[nt][2], p3 = Sv[nt][3];
            float h2 = __bfloat162float(__float2bfloat16_rn(p2));
            float h3 = __bfloat162float(__float2bfloat16_rn(p3));
            sPh[w0 + 8*VST] = pack_bf16(h2, h3);
            sPl[w0 + 8*VST] = pack_bf16(p2 - h2, p3 - h3);
        }
        __syncwarp();

        #pragma unroll
        for (int kc2 = 0; kc2 < 8; kc2++) {
            int po = pbase + kc2 * 8;
            uint32_t ph[4], pl[4];
            ph[0] = sPh[po];              ph[1] = sPh[po + 8*VST];
            ph[2] = sPh[po + 4];          ph[3] = sPh[po + 8*VST + 4];
            pl[0] = sPl[po];              pl[1] = sPl[po + 8*VST];
            pl[2] = sPl[po + 4];          pl[3] = sPl[po + 8*VST + 4];
            #pragma unroll
            for (int nt2 = 0; nt2 < 8; nt2++) {
                int vo = (nt2 * 8 + r) * VST + kc2 * 8 + c4;
                uint32_t vh0 = sVh[vo], vh1 = sVh[vo + 4];
                uint32_t vl0 = sVl[vo], vl1 = sVl[vo + 4];
                mma_bf16(O[nt2], ph, vh0, vh1);
                mma_bf16(O[nt2], ph, vl0, vl1);
                mma_bf16(O[nt2], pl, vh0, vh1);
            }
        }
    }

    const int b = bh >> 4, h = bh & 15;
    const float inv0 = 1.0f / lrow[0];
    const float inv1 = 1.0f / lrow[1];
    const int row0g = q0 + wid * 16 + r;
    const int row1g = row0g + 8;
    #pragma unroll
    for (int nt2 = 0; nt2 < 8; nt2++) {
        int col = h * DK + nt2 * 8 + c4 * 2;
        float v00 = O[nt2][0] * inv0, v01 = O[nt2][1] * inv0;
        float v10 = O[nt2][2] * inv1, v11 = O[nt2][3] * inv1;
        float h00 = __bfloat162float(__float2bfloat16_rn(v00));
        float h01 = __bfloat162float(__float2bfloat16_rn(v01));
        float h10 = __bfloat162float(__float2bfloat16_rn(v10));
        float h11 = __bfloat162float(__float2bfloat16_rn(v11));
        size_t o0 = (size_t)(b * SS + row0g) * DD + col;
        size_t o1 = (size_t)(b * SS + row1g) * DD + col;
        *(uint32_t*)&ohi[o0] = pack_bf16(h00, h01);
        *(uint32_t*)&olo[o0] = pack_bf16(v00 - h00, v01 - h01);
        *(uint32_t*)&ohi[o1] = pack_bf16(h10, h11);
        *(uint32_t*)&olo[o1] = pack_bf16(v10 - h10, v11 - h11);
    }
}

// ---------------- launch --------------------------------------------------------
extern "C" void kernel_launch(void* const* d_in, const int* in_sizes, int n_in,
                              void* d_out, int out_size)
{
    (void)in_sizes; (void)n_in; (void)out_size;
    const float* x  = (const float*)d_in[0];
    const float* Wq = (const float*)d_in[1];
    const float* Wk = (const float*)d_in[2];
    const float* Wv = (const float*)d_in[3];
    const float* Wo = (const float*)d_in[4];
    const int*   tp = (const int*)d_in[5];
    float* out = (float*)d_out;

    float *qb, *kb, *vb, *ct, *st;
    __nv_bfloat16 *xhi, *xlo, *wchi, *wclo, *wohi, *wolo, *abhi, *ablo;
    cudaGetSymbolAddress((void**)&qb, g_qbuf);
    cudaGetSymbolAddress((void**)&kb, g_kbuf);
    cudaGetSymbolAddress((void**)&vb, g_vbuf);
    cudaGetSymbolAddress((void**)&ct, g_ct);
    cudaGetSymbolAddress((void**)&st, g_st);
    cudaGetSymbolAddress((void**)&xhi, g_xhi);   cudaGetSymbolAddress((void**)&xlo, g_xlo);
    cudaGetSymbolAddress((void**)&wchi, g_wchi); cudaGetSymbolAddress((void**)&wclo, g_wclo);
    cudaGetSymbolAddress((void**)&wohi, g_wohi); cudaGetSymbolAddress((void**)&wolo, g_wolo);
    cudaGetSymbolAddress((void**)&abhi, g_abhi); cudaGetSymbolAddress((void**)&ablo, g_ablo);

    cudaFuncSetAttribute(gemm_mma3_kernel, cudaFuncAttributeMaxDynamicSharedMemorySize,
                         G2_SMEM_BYTES);
    cudaFuncSetAttribute(attn_mma_kernel, cudaFuncAttributeMaxDynamicSharedMemorySize,
                         ATTN_SMEM_BYTES);

    const int ntot = NX4 + 4 * NW4;
    cvt_all_kernel<<<(ntot + 255)/256, 256>>>(x, Wq, Wk, Wv, Wo,
                                              xhi, xlo, wchi, wclo, wohi, wolo);
    rope_tab_kernel<<<(BB*SS*32 + 255)/256, 256>>>(tp, ct, st);

    gemm_mma3_kernel<<<dim3(24, (BB*SS)/128), 512, G2_SMEM_BYTES>>>(
        xhi, xlo, wchi, wclo, ct, st, qb, kb, vb, nullptr, 3);

    attn_mma_kernel<<<dim3(SS / 128, BB * HH), 256, ATTN_SMEM_BYTES>>>(qb, kb, vb, abhi, ablo);

    gemm_mma3_kernel<<<dim3(8, (BB*SS)/128), 512, G2_SMEM_BYTES>>>(
        abhi, ablo, wohi, wolo, ct, st, nullptr, nullptr, nullptr, out, 2);
}

// round 7
// speedup vs baseline: 1.2788x; 1.2788x over previous
#include <cuda_runtime.h>
#include <cuda_bf16.h>
#include <math.h>
#include <math_constants.h>
#include <cstdint>

#define BB 2
#define SS 2048
#define DD 1024
#define HH 16
#define DK 64

// ---------------- scratch (allocation-free: __device__ globals) ----------------
__device__ float g_ct[BB*SS*32];
__device__ float g_st[BB*SS*32];
__device__ __nv_bfloat16 g_xhi[BB*SS*DD], g_xlo[BB*SS*DD];
__device__ __nv_bfloat16 g_wchi[3*DD*DD], g_wclo[3*DD*DD];   // Wq|Wk|Wv
__device__ __nv_bfloat16 g_wohi[DD*DD],  g_wolo[DD*DD];
__device__ __nv_bfloat16 g_qhi[BB*HH*SS*DK], g_qlo[BB*HH*SS*DK];  // headed, CSC*rope
__device__ __nv_bfloat16 g_khi[BB*HH*SS*DK], g_klo[BB*HH*SS*DK];  // headed, rope
__device__ __nv_bfloat16 g_vhi[BB*HH*SS*DK], g_vlo[BB*HH*SS*DK];  // headed
__device__ __nv_bfloat16 g_abhi[BB*SS*DD], g_ablo[BB*SS*DD];

// ======================= helpers ================================================
__device__ __forceinline__ uint32_t smem_u32(const void* p) {
    uint32_t a;
    asm("{ .reg .u64 t; cvta.to.shared.u64 t, %1; cvt.u32.u64 %0, t; }" : "=r"(a) : "l"(p));
    return a;
}
__device__ __forceinline__ uint32_t pack_bf16(float a, float b) {
    __nv_bfloat16 ha = __float2bfloat16_rn(a);
    __nv_bfloat16 hb = __float2bfloat16_rn(b);
    return (uint32_t)__bfloat16_as_ushort(ha) | ((uint32_t)__bfloat16_as_ushort(hb) << 16);
}
__device__ __forceinline__ void mma_bf16(float c[4], const uint32_t a[4],
                                         uint32_t b0, uint32_t b1) {
    asm volatile(
        "mma.sync.aligned.m16n8k16.row.col.f32.bf16.bf16.f32 "
        "{%0,%1,%2,%3},{%4,%5,%6,%7},{%8,%9},{%0,%1,%2,%3};"
        : "+f"(c[0]), "+f"(c[1]), "+f"(c[2]), "+f"(c[3])
        : "r"(a[0]), "r"(a[1]), "r"(a[2]), "r"(a[3]), "r"(b0), "r"(b1));
}
__device__ __forceinline__ void split_pack(float a, float b, uint32_t& hi, uint32_t& lo) {
    float ha = __bfloat162float(__float2bfloat16_rn(a));
    float hb = __bfloat162float(__float2bfloat16_rn(b));
    hi = pack_bf16(ha, hb);
    lo = pack_bf16(a - ha, b - hb);
}
__device__ __forceinline__ void store_hilo(uint32_t* hiArr, uint32_t* loArr,
                                           int base, float4 v) {
    uint32_t h0, l0, h1, l1;
    split_pack(v.x, v.y, h0, l0);
    split_pack(v.z, v.w, h1, l1);
    *(uint2*)&hiArr[base] = make_uint2(h0, h1);
    *(uint2*)&loArr[base] = make_uint2(l0, l1);
}
__device__ __forceinline__ float exp2a(float x) {
    x = fmaxf(x, -126.0f);
    float z = x + 12582912.0f;
    uint32_t iz = __float_as_uint(z);
    float f = x - (z - 12582912.0f);
    float p = 0.0013333558f;
    p = fmaf(p, f, 0.0096180885f);
    p = fmaf(p, f, 0.0555041087f);
    p = fmaf(p, f, 0.2402265069f);
    p = fmaf(p, f, 0.6931471806f);
    p = fmaf(p, f, 1.0f);
    return __uint_as_float(__float_as_uint(p) + (iz << 23));
}
__device__ __forceinline__ void cp16(uint32_t dst, const void* src) {
    asm volatile("cp.async.ca.shared.global [%0], [%1], 16;" :: "r"(dst), "l"(src));
}
#define CP_COMMIT() asm volatile("cp.async.commit_group;" ::: "memory")
#define CP_WAIT0()  asm volatile("cp.async.wait_group 0;" ::: "memory")
#define LDSM4(d, a) \
    asm volatile("ldmatrix.sync.aligned.m8n8.x4.shared.b16 {%0,%1,%2,%3},[%4];" \
        : "=r"((d)[0]), "=r"((d)[1]), "=r"((d)[2]), "=r"((d)[3]) : "r"(a))
#define LDSM4T(d, a) \
    asm volatile("ldmatrix.sync.aligned.m8n8.x4.trans.shared.b16 {%0,%1,%2,%3},[%4];" \
        : "=r"((d)[0]), "=r"((d)[1]), "=r"((d)[2]), "=r"((d)[3]) : "r"(a))

// ======================= fused pre-pass: f32 -> bf16 hi/lo ======================
#define NX4 (BB*SS*DD/4)
#define NW4 (DD*DD/4)
__global__ void cvt_all_kernel(const float* __restrict__ x,  const float* __restrict__ Wq,
                               const float* __restrict__ Wk, const float* __restrict__ Wv,
                               const float* __restrict__ Wo,
                               __nv_bfloat16* __restrict__ xhi, __nv_bfloat16* __restrict__ xlo,
                               __nv_bfloat16* __restrict__ wchi, __nv_bfloat16* __restrict__ wclo,
                               __nv_bfloat16* __restrict__ wohi, __nv_bfloat16* __restrict__ wolo)
{
    int idx = blockIdx.x * blockDim.x + threadIdx.x;
    const float* src;
    __nv_bfloat16 *hi, *lo;
    int off;
    if (idx < NX4)              { src = x;  hi = xhi;  lo = xlo;  off = idx; }
    else if (idx < NX4 + NW4)   { src = Wq; hi = wchi; lo = wclo; off = idx - NX4; }
    else if (idx < NX4 + 2*NW4) { src = Wk; hi = wchi + DD*DD; lo = wclo + DD*DD; off = idx - NX4 - NW4; }
    else if (idx < NX4 + 3*NW4) { src = Wv; hi = wchi + 2*DD*DD; lo = wclo + 2*DD*DD; off = idx - NX4 - 2*NW4; }
    else if (idx < NX4 + 4*NW4) { src = Wo; hi = wohi; lo = wolo; off = idx - NX4 - 3*NW4; }
    else return;
    float4 v = *(const float4*)&src[(size_t)off * 4];
    uint32_t h0, l0, h1, l1;
    split_pack(v.x, v.y, h0, l0);
    split_pack(v.z, v.w, h1, l1);
    *(uint2*)&hi[(size_t)off * 4] = make_uint2(h0, h1);
    *(uint2*)&lo[(size_t)off * 4] = make_uint2(l0, l1);
}

// ======================= RoPE table =============================================
__global__ void rope_tab_kernel(const int* __restrict__ tp, float* __restrict__ ct,
                                float* __restrict__ st)
{
    int idx = blockIdx.x * blockDim.x + threadIdx.x;
    if (idx >= BB*SS*32) return;
    int m = idx >> 5;
    int p = idx & 31;
    float inv = powf(10000.0f, -(float)(2*p) * (1.0f/64.0f));
    float freq = (float)tp[m] * inv;
    float sn, cs;
    sincosf(freq, &sn, &cs);
    ct[idx] = cs;
    st[idx] = sn;
}

// ======================= GEMM: 256 thr, cp.async double-buffer ==================
// mode 3: fused QKV (seg via blockIdx.x>>3), epilogue -> bf16 hi/lo headed bufs
// mode 2: Wo -> f32 out
#define SROW 20
#define G2_ARR 2560
#define G2_STAGE (4*G2_ARR)
#define G2_SMEM_BYTES (2*G2_STAGE*4)
#define CSCALE (0.125f * 1.44269504088896f)

__global__ __launch_bounds__(256)
void gemm_mma4_kernel(const __nv_bfloat16* __restrict__ Ahi, const __nv_bfloat16* __restrict__ Alo,
                      const __nv_bfloat16* __restrict__ Bh,  const __nv_bfloat16* __restrict__ Bl,
                      const float* __restrict__ ct, const float* __restrict__ st,
                      __nv_bfloat16* __restrict__ qhi, __nv_bfloat16* __restrict__ qlo,
                      __nv_bfloat16* __restrict__ khi, __nv_bfloat16* __restrict__ klo,
                      __nv_bfloat16* __restrict__ vhi, __nv_bfloat16* __restrict__ vlo,
                      float* __restrict__ outp, int mode)
{
    extern __shared__ uint32_t su2[];
    const uint32_t sbase = smem_u32(su2);

    const int tid = threadIdx.x;
    const int wid = tid >> 5;
    const int lid = tid & 31;
    const int wm = wid >> 2;
    const int wn = wid & 3;
    const int r  = lid >> 2;
    const int c4 = lid & 3;
    const int m0 = blockIdx.y * 128;

    int n0, seg;
    const __nv_bfloat16 *bhp = Bh, *blp = Bl;
    if (mode == 3) {
        seg = blockIdx.x >> 3;
        n0 = (blockIdx.x & 7) * 128;
        bhp += (size_t)seg * DD * DD;
        blp += (size_t)seg * DD * DD;
    } else {
        seg = 3;
        n0 = blockIdx.x * 128;
    }

    const int prow = tid >> 2;
    const int pch  = tid & 3;

    float C[4][4][4];
    #pragma unroll
    for (int mt = 0; mt < 4; mt++)
        #pragma unroll
        for (int nt = 0; nt < 4; nt++)
            #pragma unroll
            for (int q = 0; q < 4; q++) C[mt][nt][q] = 0.f;

    auto prefetch = [&](int kt, int st2) {
        const int k0 = kt * 32;
        #pragma unroll
        for (int i = 0; i < 2; i++) {
            int row = prow + i * 64;
            uint32_t d = sbase + (uint32_t)(st2 * G2_STAGE + row * SROW + pch * 4) * 4u;
            size_t goA = (size_t)(m0 + row) * DD + k0 + pch * 8;
            size_t goB = (size_t)(n0 + row) * DD + k0 + pch * 8;
            cp16(d,                Ahi + goA);
            cp16(d + G2_ARR * 4u,  Alo + goA);
            cp16(d + 2u*G2_ARR*4u, bhp + goB);
            cp16(d + 3u*G2_ARR*4u, blp + goB);
        }
        CP_COMMIT();
    };

    prefetch(0, 0);

    const int aoff = (wm * 64 + r) * SROW + c4;
    const int boff = (wn * 32 + r) * SROW + c4;

    for (int kt = 0; kt < 32; kt++) {
        CP_WAIT0();
        __syncthreads();
        if (kt < 31) prefetch(kt + 1, (kt + 1) & 1);

        uint32_t* sAhi = su2 + (kt & 1) * G2_STAGE;
        uint32_t* sAlo = sAhi + G2_ARR;
        uint32_t* sBhi = sAlo + G2_ARR;
        uint32_t* sBlo = sBhi + G2_ARR;

        #pragma unroll
        for (int kc = 0; kc < 2; kc++) {
            uint32_t bh[4][2], bl[4][2];
            #pragma unroll
            for (int nt = 0; nt < 4; nt++) {
                int bb = boff + nt * 8 * SROW + kc * 8;
                bh[nt][0] = sBhi[bb];     bh[nt][1] = sBhi[bb + 4];
                bl[nt][0] = sBlo[bb];     bl[nt][1] = sBlo[bb + 4];
            }
            #pragma unroll
            for (int mt = 0; mt < 4; mt++) {
                int ab = aoff + mt * 16 * SROW + kc * 8;
                uint32_t ah[4], al[4];
                ah[0] = sAhi[ab];             ah[1] = sAhi[ab + 8 * SROW];
                ah[2] = sAhi[ab + 4];         ah[3] = sAhi[ab + 8 * SROW + 4];
                al[0] = sAlo[ab];             al[1] = sAlo[ab + 8 * SROW];
                al[2] = sAlo[ab + 4];         al[3] = sAlo[ab + 8 * SROW + 4];
                #pragma unroll
                for (int nt = 0; nt < 4; nt++) {
                    mma_bf16(C[mt][nt], ah, bh[nt][0], bh[nt][1]);
                    mma_bf16(C[mt][nt], ah, bl[nt][0], bl[nt][1]);
                    mma_bf16(C[mt][nt], al, bh[nt][0], bh[nt][1]);
                }
            }
        }
    }

    // ---------------- epilogue ----------------
    __nv_bfloat16 *hsel = qhi, *lsel = qlo;
    if (seg == 1) { hsel = khi; lsel = klo; }
    if (seg == 2) { hsel = vhi; lsel = vlo; }

    #pragma unroll
    for (int mt = 0; mt < 4; mt++) {
        const int row0 = m0 + wm * 64 + mt * 16 + r;
        const int row1 = row0 + 8;
        #pragma unroll
        for (int nt = 0; nt < 4; nt++) {
            const int ncol = n0 + wn * 32 + nt * 8 + c4 * 2;
            float v00 = C[mt][nt][0], v01 = C[mt][nt][1];
            float v10 = C[mt][nt][2], v11 = C[mt][nt][3];
            if (seg == 3) {
                *(float2*)&outp[(size_t)row0 * DD + ncol] = make_float2(v00, v01);
                *(float2*)&outp[(size_t)row1 * DD + ncol] = make_float2(v10, v11);
            } else {
                const int h   = ncol >> 6;
                const int dk0 = ncol & 63;
                if (seg < 2) {
                    const int p = dk0 >> 1;
                    float cs0 = ct[(size_t)row0 * 32 + p], sn0 = st[(size_t)row0 * 32 + p];
                    float cs1 = ct[(size_t)row1 * 32 + p], sn1 = st[(size_t)row1 * 32 + p];
                    float t00 = cs0 * v00 - sn0 * v01;
                    float t01 = sn0 * v00 + cs0 * v01;
                    float t10 = cs1 * v10 - sn1 * v11;
                    float t11 = sn1 * v10 + cs1 * v11;
                    v00 = t00; v01 = t01; v10 = t10; v11 = t11;
                    if (seg == 0) { v00 *= CSCALE; v01 *= CSCALE; v10 *= CSCALE; v11 *= CSCALE; }
                }
                const int b0r = row0 >> 11, s0 = row0 & (SS - 1);
                const int b1r = row1 >> 11, s1 = row1 & (SS - 1);
                size_t hb0 = ((size_t)(b0r * HH + h) * SS + s0) * 32 + (dk0 >> 1);
                size_t hb1 = ((size_t)(b1r * HH + h) * SS + s1) * 32 + (dk0 >> 1);
                uint32_t h0, l0, h1, l1;
                split_pack(v00, v01, h0, l0);
                split_pack(v10, v11, h1, l1);
                ((uint32_t*)hsel)[hb0] = h0;
                ((uint32_t*)lsel)[hb0] = l0;
                ((uint32_t*)hsel)[hb1] = h1;
                ((uint32_t*)lsel)[hb1] = l1;
            }
        }
    }
}

// ======================= flash attention v2: LDSM + cp.async ====================
// smem rows: 144 B (36 u32) per 64-dk row. Q: 1 buf hi/lo; K,V: 2 bufs hi/lo.
#define ROWB 144
#define AB_LO 18432            // bytes: 128*144
#define AB_Q  0
#define AB_K  36864
#define AB_V  110592
#define ATTN_SMEM_BYTES 184320

__global__ __launch_bounds__(256)
void attn_mma2_kernel(const __nv_bfloat16* __restrict__ qhi, const __nv_bfloat16* __restrict__ qlo,
                      const __nv_bfloat16* __restrict__ khi, const __nv_bfloat16* __restrict__ klo,
                      const __nv_bfloat16* __restrict__ vhi, const __nv_bfloat16* __restrict__ vlo,
                      __nv_bfloat16* __restrict__ ohi, __nv_bfloat16* __restrict__ olo)
{
    extern __shared__ uint32_t su[];
    const uint32_t sbase = smem_u32(su);

    const int tid = threadIdx.x;
    const int wid = tid >> 5;
    const int lid = tid & 31;
    const int r   = lid >> 2;
    const int c4  = lid & 3;
    const int i8  = lid & 7;       // ldmatrix row-within-matrix
    const int m8  = lid >> 3;      // ldmatrix matrix id
    const int bh  = blockIdx.y;
    const int qt  = gridDim.x - 1 - blockIdx.x;
    const int q0  = qt * 128;

    const __nv_bfloat16* qhp = qhi + (size_t)bh * SS * DK;
    const __nv_bfloat16* qlp = qlo + (size_t)bh * SS * DK;
    const __nv_bfloat16* khp = khi + (size_t)bh * SS * DK;
    const __nv_bfloat16* klp = klo + (size_t)bh * SS * DK;
    const __nv_bfloat16* vhp = vhi + (size_t)bh * SS * DK;
    const __nv_bfloat16* vlp = vlo + (size_t)bh * SS * DK;

    auto tile_cp = [&](uint32_t dstB, const __nv_bfloat16* src, int row0g) {
        #pragma unroll
        for (int t = 0; t < 4; t++) {
            int id = tid + t * 256;
            int row = id >> 3, ch = id & 7;
            cp16(dstB + row * ROWB + ch * 16, src + (size_t)(row0g + row) * DK + ch * 8);
        }
    };
    auto prefetch_kv = [&](int kt, int buf) {
        int k0 = kt * 128;
        uint32_t kb = sbase + AB_K + buf * 36864;
        uint32_t vb = sbase + AB_V + buf * 36864;
        tile_cp(kb,          khp, k0);
        tile_cp(kb + AB_LO,  klp, k0);
        tile_cp(vb,          vhp, k0);
        tile_cp(vb + AB_LO,  vlp, k0);
        CP_COMMIT();
    };

    // Q once + tile 0
    tile_cp(sbase + AB_Q,         qhp, q0);
    tile_cp(sbase + AB_Q + AB_LO, qlp, q0);
    prefetch_kv(0, 0);

    float mrow[2] = {-CUDART_INF_F, -CUDART_INF_F};
    float lrow[2] = {0.f, 0.f};
    float O[8][4];
    #pragma unroll
    for (int a = 0; a < 8; a++)
        #pragma unroll
        for (int b2 = 0; b2 < 4; b2++) O[a][b2] = 0.f;

    // lane-fixed ldmatrix address components (bytes)
    const uint32_t qa_lane = sbase + AB_Q +
        (uint32_t)(wid * 16 + i8 + ((m8 & 1) << 3)) * ROWB + ((m8 & 2) << 3);
    const uint32_t kb_lane = (uint32_t)(i8 + ((m8 & 2) << 2)) * ROWB + ((m8 & 1) << 4);
    const uint32_t va_lane = (uint32_t)(i8 + ((m8 & 1) << 3)) * ROWB + ((m8 & 2) << 3);

    for (int kt = 0; kt <= qt; kt++) {
        CP_WAIT0();
        __syncthreads();
        if (kt < qt) prefetch_kv(kt + 1, (kt + 1) & 1);

        const uint32_t kbuf = sbase + AB_K + (kt & 1) * 36864;
        const uint32_t vbuf = sbase + AB_V + (kt & 1) * 36864;

        // ---- S = Q K^T (3-pass) ----
        float Sv[16][4];
        #pragma unroll
        for (int nt = 0; nt < 16; nt++)
            #pragma unroll
            for (int q = 0; q < 4; q++) Sv[nt][q] = 0.f;

        #pragma unroll
        for (int kc = 0; kc < 4; kc++) {
            uint32_t ah[4], al[4];
            LDSM4(ah, qa_lane + kc * 32);
            LDSM4(al, qa_lane + AB_LO + kc * 32);
            #pragma unroll
            for (int ntp = 0; ntp < 8; ntp++) {
                uint32_t ka = kbuf + kb_lane + ntp * (16 * ROWB) + kc * 32;
                uint32_t bhv[4], blv[4];
                LDSM4(bhv, ka);
                LDSM4(blv, ka + AB_LO);
                mma_bf16(Sv[2*ntp],   ah, bhv[0], bhv[1]);
                mma_bf16(Sv[2*ntp+1], ah, bhv[2], bhv[3]);
                mma_bf16(Sv[2*ntp],   ah, blv[0], blv[1]);
                mma_bf16(Sv[2*ntp+1], ah, blv[2], blv[3]);
                mma_bf16(Sv[2*ntp],   al, bhv[0], bhv[1]);
                mma_bf16(Sv[2*ntp+1], al, bhv[2], bhv[3]);
            }
        }

        // ---- causal mask on diagonal tile ----
        if (kt == qt) {
            int row0 = wid * 16 + r;
            int row1 = row0 + 8;
            #pragma unroll
            for (int nt = 0; nt < 16; nt++) {
                int col = nt * 8 + c4 * 2;
                if (col     > row0) Sv[nt][0] = -1e30f;
                if (col + 1 > row0) Sv[nt][1] = -1e30f;
                if (col     > row1) Sv[nt][2] = -1e30f;
                if (col + 1 > row1) Sv[nt][3] = -1e30f;
            }
        }

        // ---- online softmax (exp2 domain) ----
        #pragma unroll
        for (int hrow = 0; hrow < 2; hrow++) {
            float tm = -CUDART_INF_F;
            #pragma unroll
            for (int nt = 0; nt < 16; nt++) {
                tm = fmaxf(tm, Sv[nt][2*hrow]);
                tm = fmaxf(tm, Sv[nt][2*hrow + 1]);
            }
            tm = fmaxf(tm, __shfl_xor_sync(0xffffffffu, tm, 1));
            tm = fmaxf(tm, __shfl_xor_sync(0xffffffffu, tm, 2));
            float mn = fmaxf(mrow[hrow], tm);
            float alpha = exp2a(mrow[hrow] - mn);
            float ps = 0.f;
            #pragma unroll
            for (int nt = 0; nt < 16; nt++) {
                float p0 = exp2a(Sv[nt][2*hrow]     - mn);
                float p1 = exp2a(Sv[nt][2*hrow + 1] - mn);
                Sv[nt][2*hrow]     = p0;
                Sv[nt][2*hrow + 1] = p1;
                ps += p0 + p1;
            }
            ps += __shfl_xor_sync(0xffffffffu, ps, 1);
            ps += __shfl_xor_sync(0xffffffffu, ps, 2);
            lrow[hrow] = lrow[hrow] * alpha + ps;
            mrow[hrow] = mn;
            #pragma unroll
            for (int nt2 = 0; nt2 < 8; nt2++) {
                O[nt2][2*hrow]     *= alpha;
                O[nt2][2*hrow + 1] *= alpha;
            }
        }

        // ---- O += P V (3-pass); P fragments built in registers ----
        #pragma unroll
        for (int kc2 = 0; kc2 < 8; kc2++) {
            uint32_t pah[4], pal[4];
            split_pack(Sv[2*kc2][0],   Sv[2*kc2][1],   pah[0], pal[0]);
            split_pack(Sv[2*kc2][2],   Sv[2*kc2][3],   pah[1], pal[1]);
            split_pack(Sv[2*kc2+1][0], Sv[2*kc2+1][1], pah[2], pal[2]);
            split_pack(Sv[2*kc2+1][2], Sv[2*kc2+1][3], pah[3], pal[3]);
            uint32_t va0 = vbuf + va_lane + kc2 * (16 * ROWB);
            #pragma unroll
            for (int g = 0; g < 4; g++) {
                uint32_t bhv[4], blv[4];
                LDSM4T(bhv, va0 + g * 32);
                LDSM4T(blv, va0 + g * 32 + AB_LO);
                mma_bf16(O[2*g],   pah, bhv[0], bhv[1]);
                mma_bf16(O[2*g+1], pah, bhv[2], bhv[3]);
                mma_bf16(O[2*g],   pah, blv[0], blv[1]);
                mma_bf16(O[2*g+1], pah, blv[2], blv[3]);
                mma_bf16(O[2*g],   pal, bhv[0], bhv[1]);
                mma_bf16(O[2*g+1], pal, bhv[2], bhv[3]);
            }
        }
    }

    // ---- normalize + write hi/lo bf16 ----
    const int b = bh >> 4, h = bh & 15;
    const float inv0 = 1.0f / lrow[0];
    const float inv1 = 1.0f / lrow[1];
    const int row0g = q0 + wid * 16 + r;
    const int row1g = row0g + 8;
    #pragma unroll
    for (int nt2 = 0; nt2 < 8; nt2++) {
        int col = h * DK + nt2 * 8 + c4 * 2;
        float v00 = O[nt2][0] * inv0, v01 = O[nt2][1] * inv0;
        float v10 = O[nt2][2] * inv1, v11 = O[nt2][3] * inv1;
        uint32_t h0, l0, h1, l1;
        split_pack(v00, v01, h0, l0);
        split_pack(v10, v11, h1, l1);
        size_t o0 = ((size_t)(b * SS + row0g) * DD + col) >> 1;
        size_t o1 = ((size_t)(b * SS + row1g) * DD + col) >> 1;
        ((uint32_t*)ohi)[o0] = h0;
        ((uint32_t*)olo)[o0] = l0;
        ((uint32_t*)ohi)[o1] = h1;
        ((uint32_t*)olo)[o1] = l1;
    }
}

// ---------------- launch --------------------------------------------------------
extern "C" void kernel_launch(void* const* d_in, const int* in_sizes, int n_in,
                              void* d_out, int out_size)
{
    (void)in_sizes; (void)n_in; (void)out_size;
    const float* x  = (const float*)d_in[0];
    const float* Wq = (const float*)d_in[1];
    const float* Wk = (const float*)d_in[2];
    const float* Wv = (const float*)d_in[3];
    const float* Wo = (const float*)d_in[4];
    const int*   tp = (const int*)d_in[5];
    float* out = (float*)d_out;

    float *ct, *st;
    __nv_bfloat16 *xhi, *xlo, *wchi, *wclo, *wohi, *wolo;
    __nv_bfloat16 *qhi, *qlo, *khi, *klo, *vhi, *vlo, *abhi, *ablo;
    cudaGetSymbolAddress((void**)&ct, g_ct);
    cudaGetSymbolAddress((void**)&st, g_st);
    cudaGetSymbolAddress((void**)&xhi, g_xhi);   cudaGetSymbolAddress((void**)&xlo, g_xlo);
    cudaGetSymbolAddress((void**)&wchi, g_wchi); cudaGetSymbolAddress((void**)&wclo, g_wclo);
    cudaGetSymbolAddress((void**)&wohi, g_wohi); cudaGetSymbolAddress((void**)&wolo, g_wolo);
    cudaGetSymbolAddress((void**)&qhi, g_qhi);   cudaGetSymbolAddress((void**)&qlo, g_qlo);
    cudaGetSymbolAddress((void**)&khi, g_khi);   cudaGetSymbolAddress((void**)&klo, g_klo);
    cudaGetSymbolAddress((void**)&vhi, g_vhi);   cudaGetSymbolAddress((void**)&vlo, g_vlo);
    cudaGetSymbolAddress((void**)&abhi, g_abhi); cudaGetSymbolAddress((void**)&ablo, g_ablo);

    cudaFuncSetAttribute(gemm_mma4_kernel, cudaFuncAttributeMaxDynamicSharedMemorySize,
                         G2_SMEM_BYTES);
    cudaFuncSetAttribute(attn_mma2_kernel, cudaFuncAttributeMaxDynamicSharedMemorySize,
                         ATTN_SMEM_BYTES);

    const int ntot = NX4 + 4 * NW4;
    cvt_all_kernel<<<(ntot + 255)/256, 256>>>(x, Wq, Wk, Wv, Wo,
                                              xhi, xlo, wchi, wclo, wohi, wolo);
    rope_tab_kernel<<<(BB*SS*32 + 255)/256, 256>>>(tp, ct, st);

    // fused QKV projection
    gemm_mma4_kernel<<<dim3(24, (BB*SS)/128), 256, G2_SMEM_BYTES>>>(
        xhi, xlo, wchi, wclo, ct, st,
        qhi, qlo, khi, klo, vhi, vlo, nullptr, 3);

    attn_mma2_kernel<<<dim3(SS / 128, BB * HH), 256, ATTN_SMEM_BYTES>>>(
        qhi, qlo, khi, klo, vhi, vlo, abhi, ablo);

    // output projection
    gemm_mma4_kernel<<<dim3(8, (BB*SS)/128), 256, G2_SMEM_BYTES>>>(
        abhi, ablo, wohi, wolo, ct, st,
        nullptr, nullptr, nullptr, nullptr, nullptr, nullptr, out, 2);
}

// round 8
// speedup vs baseline: 1.8642x; 1.4578x over previous
#include <cuda_runtime.h>
#include <cuda_bf16.h>
#include <cuda_fp16.h>
#include <math.h>
#include <math_constants.h>
#include <cstdint>

#define BB 2
#define SS 2048
#define DD 1024
#define HH 16
#define DK 64

// ---------------- scratch (allocation-free: __device__ globals) ----------------
__device__ float g_ct[BB*SS*32];
__device__ float g_st[BB*SS*32];
__device__ __half g_xhi[BB*SS*DD], g_xlo[BB*SS*DD];
__device__ __half g_wc[3*DD*DD];                    // Wq|Wk|Wv single fp16
__device__ __half g_wo[DD*DD];                      // Wo single fp16
__device__ __half g_qhi[BB*HH*SS*DK], g_qlo[BB*HH*SS*DK];  // headed, rope'd
__device__ __half g_kk[BB*HH*SS*DK];                // headed, rope'd, single
__device__ __half g_vv[BB*HH*SS*DK];                // headed, single
__device__ __half g_abhi[BB*SS*DD], g_ablo[BB*SS*DD];

// ======================= helpers ================================================
__device__ __forceinline__ uint32_t smem_u32(const void* p) {
    uint32_t a;
    asm("{ .reg .u64 t; cvta.to.shared.u64 t, %1; cvt.u32.u64 %0, t; }" : "=r"(a) : "l"(p));
    return a;
}
__device__ __forceinline__ uint32_t pack_h(float a, float b) {
    __half2 h = __floats2half2_rn(a, b);
    return *(uint32_t*)&h;
}
__device__ __forceinline__ void split_pack_h(float a, float b, uint32_t& hi, uint32_t& lo) {
    __half ha = __float2half_rn(a);
    __half hb = __float2half_rn(b);
    hi = (uint32_t)__half_as_ushort(ha) | ((uint32_t)__half_as_ushort(hb) << 16);
    lo = pack_h(a - __half2float(ha), b - __half2float(hb));
}
__device__ __forceinline__ void mma_f16(float c[4], const uint32_t a[4],
                                        uint32_t b0, uint32_t b1) {
    asm volatile(
        "mma.sync.aligned.m16n8k16.row.col.f32.f16.f16.f32 "
        "{%0,%1,%2,%3},{%4,%5,%6,%7},{%8,%9},{%0,%1,%2,%3};"
        : "+f"(c[0]), "+f"(c[1]), "+f"(c[2]), "+f"(c[3])
        : "r"(a[0]), "r"(a[1]), "r"(a[2]), "r"(a[3]), "r"(b0), "r"(b1));
}
__device__ __forceinline__ float exp2a(float x) {
    x = fmaxf(x, -126.0f);
    float z = x + 12582912.0f;
    uint32_t iz = __float_as_uint(z);
    float f = x - (z - 12582912.0f);
    float p = 0.0013333558f;
    p = fmaf(p, f, 0.0096180885f);
    p = fmaf(p, f, 0.0555041087f);
    p = fmaf(p, f, 0.2402265069f);
    p = fmaf(p, f, 0.6931471806f);
    p = fmaf(p, f, 1.0f);
    return __uint_as_float(__float_as_uint(p) + (iz << 23));
}
__device__ __forceinline__ void cp16(uint32_t dst, const void* src) {
    asm volatile("cp.async.ca.shared.global [%0], [%1], 16;" :: "r"(dst), "l"(src));
}
#define CP_COMMIT() asm volatile("cp.async.commit_group;" ::: "memory")
#define CP_WAIT0()  asm volatile("cp.async.wait_group 0;" ::: "memory")
#define LDSM4(d, a) \
    asm volatile("ldmatrix.sync.aligned.m8n8.x4.shared.b16 {%0,%1,%2,%3},[%4];" \
        : "=r"((d)[0]), "=r"((d)[1]), "=r"((d)[2]), "=r"((d)[3]) : "r"(a))
#define LDSM4T(d, a) \
    asm volatile("ldmatrix.sync.aligned.m8n8.x4.trans.shared.b16 {%0,%1,%2,%3},[%4];" \
        : "=r"((d)[0]), "=r"((d)[1]), "=r"((d)[2]), "=r"((d)[3]) : "r"(a))

// ======================= pre-pass conversions ===================================
#define NX4 (BB*SS*DD/4)
#define NW4 (DD*DD/4)
__global__ void cvt_all_kernel(const float* __restrict__ x,  const float* __restrict__ Wq,
                               const float* __restrict__ Wk, const float* __restrict__ Wv,
                               const float* __restrict__ Wo,
                               __half* __restrict__ xhi, __half* __restrict__ xlo,
                               __half* __restrict__ wc, __half* __restrict__ wo)
{
    int idx = blockIdx.x * blockDim.x + threadIdx.x;
    if (idx < NX4) {
        float4 v = *(const float4*)&x[(size_t)idx * 4];
        uint32_t h0, l0, h1, l1;
        split_pack_h(v.x, v.y, h0, l0);
        split_pack_h(v.z, v.w, h1, l1);
        *(uint2*)&xhi[(size_t)idx * 4] = make_uint2(h0, h1);
        *(uint2*)&xlo[(size_t)idx * 4] = make_uint2(l0, l1);
        return;
    }
    const float* src;
    __half* dst;
    int off;
    if (idx < NX4 + NW4)        { src = Wq; dst = wc;             off = idx - NX4; }
    else if (idx < NX4 + 2*NW4) { src = Wk; dst = wc + DD*DD;     off = idx - NX4 - NW4; }
    else if (idx < NX4 + 3*NW4) { src = Wv; dst = wc + 2*DD*DD;   off = idx - NX4 - 2*NW4; }
    else if (idx < NX4 + 4*NW4) { src = Wo; dst = wo;             off = idx - NX4 - 3*NW4; }
    else return;
    float4 v = *(const float4*)&src[(size_t)off * 4];
    *(uint2*)&dst[(size_t)off * 4] = make_uint2(pack_h(v.x, v.y), pack_h(v.z, v.w));
}

// ======================= RoPE table =============================================
__global__ void rope_tab_kernel(const int* __restrict__ tp, float* __restrict__ ct,
                                float* __restrict__ st)
{
    int idx = blockIdx.x * blockDim.x + threadIdx.x;
    if (idx >= BB*SS*32) return;
    int m = idx >> 5;
    int p = idx & 31;
    float inv = powf(10000.0f, -(float)(2*p) * (1.0f/64.0f));
    float freq = (float)tp[m] * inv;
    float sn, cs;
    sincosf(freq, &sn, &cs);
    ct[idx] = cs;
    st[idx] = sn;
}

// ======================= GEMM v5: fp16 2-pass, warp 64x64, 128 thr ==============
// C = A @ B^T; A = Ahi+Alo (fp16 pair), B single fp16.
// mode 3: fused QKV (seg = blockIdx.x>>3), epilogue -> headed fp16 bufs
// mode 2: Wo -> f32 out
#define SROW 20
#define G5_ARR 2560
#define G5_STAGE (3*G5_ARR)
#define G5_SMEM_BYTES (2*G5_STAGE*4)   // 61440

__global__ __launch_bounds__(128, 2)
void gemm_mma5_kernel(const __half* __restrict__ Ahi, const __half* __restrict__ Alo,
                      const __half* __restrict__ Bh,
                      const float* __restrict__ ct, const float* __restrict__ st,
                      __half* __restrict__ qhi, __half* __restrict__ qlo,
                      __half* __restrict__ kkp, __half* __restrict__ vvp,
                      float* __restrict__ outp, int mode)
{
    extern __shared__ uint32_t su2[];
    const uint32_t sbase = smem_u32(su2);

    const int tid = threadIdx.x;
    const int wid = tid >> 5;
    const int lid = tid & 31;
    const int wm = wid >> 1;          // 0..1
    const int wn = wid & 1;           // 0..1
    const int r  = lid >> 2;
    const int c4 = lid & 3;
    const int m0 = blockIdx.y * 128;

    int n0, seg;
    const __half* bp = Bh;
    if (mode == 3) {
        seg = blockIdx.x >> 3;
        n0 = (blockIdx.x & 7) * 128;
        bp += (size_t)seg * DD * DD;
    } else {
        seg = 3;
        n0 = blockIdx.x * 128;
    }

    const int prow = tid >> 2;        // 0..31
    const int pch  = tid & 3;

    float C[4][8][4];
    #pragma unroll
    for (int mt = 0; mt < 4; mt++)
        #pragma unroll
        for (int nt = 0; nt < 8; nt++)
            #pragma unroll
            for (int q = 0; q < 4; q++) C[mt][nt][q] = 0.f;

    auto prefetch = [&](int kt, int st2) {
        const int k0 = kt * 32;
        #pragma unroll
        for (int i = 0; i < 4; i++) {
            int row = prow + i * 32;
            uint32_t d = sbase + (uint32_t)(st2 * G5_STAGE + row * SROW + pch * 4) * 4u;
            size_t goA = (size_t)(m0 + row) * DD + k0 + pch * 8;
            size_t goB = (size_t)(n0 + row) * DD + k0 + pch * 8;
            cp16(d,                Ahi + goA);
            cp16(d + G5_ARR * 4u,  Alo + goA);
            cp16(d + 2u*G5_ARR*4u, bp  + goB);
        }
        CP_COMMIT();
    };

    prefetch(0, 0);

    const int aoff = (wm * 64 + r) * SROW + c4;
    const int boff = (wn * 64 + r) * SROW + c4;

    for (int kt = 0; kt < 32; kt++) {
        CP_WAIT0();
        __syncthreads();
        if (kt < 31) prefetch(kt + 1, (kt + 1) & 1);

        uint32_t* sAhi = su2 + (kt & 1) * G5_STAGE;
        uint32_t* sAlo = sAhi + G5_ARR;
        uint32_t* sB   = sAlo + G5_ARR;

        #pragma unroll
        for (int kc = 0; kc < 2; kc++) {
            uint32_t bh[8][2];
            #pragma unroll
            for (int nt = 0; nt < 8; nt++) {
                int bb = boff + nt * 8 * SROW + kc * 8;
                bh[nt][0] = sB[bb];
                bh[nt][1] = sB[bb + 4];
            }
            #pragma unroll
            for (int mt = 0; mt < 4; mt++) {
                int ab = aoff + mt * 16 * SROW + kc * 8;
                uint32_t ah[4], al[4];
                ah[0] = sAhi[ab];             ah[1] = sAhi[ab + 8 * SROW];
                ah[2] = sAhi[ab + 4];         ah[3] = sAhi[ab + 8 * SROW + 4];
                al[0] = sAlo[ab];             al[1] = sAlo[ab + 8 * SROW];
                al[2] = sAlo[ab + 4];         al[3] = sAlo[ab + 8 * SROW + 4];
                #pragma unroll
                for (int nt = 0; nt < 8; nt++) {
                    mma_f16(C[mt][nt], ah, bh[nt][0], bh[nt][1]);
                    mma_f16(C[mt][nt], al, bh[nt][0], bh[nt][1]);
                }
            }
        }
    }

    // ---------------- epilogue ----------------
    #pragma unroll
    for (int mt = 0; mt < 4; mt++) {
        const int row0 = m0 + wm * 64 + mt * 16 + r;
        const int row1 = row0 + 8;
        #pragma unroll
        for (int nt = 0; nt < 8; nt++) {
            const int ncol = n0 + wn * 64 + nt * 8 + c4 * 2;
            float v00 = C[mt][nt][0], v01 = C[mt][nt][1];
            float v10 = C[mt][nt][2], v11 = C[mt][nt][3];
            if (seg == 3) {
                *(float2*)&outp[(size_t)row0 * DD + ncol] = make_float2(v00, v01);
                *(float2*)&outp[(size_t)row1 * DD + ncol] = make_float2(v10, v11);
            } else {
                const int h   = ncol >> 6;
                const int dk0 = ncol & 63;
                if (seg < 2) {
                    const int p = dk0 >> 1;
                    float cs0 = ct[(size_t)row0 * 32 + p], sn0 = st[(size_t)row0 * 32 + p];
                    float cs1 = ct[(size_t)row1 * 32 + p], sn1 = st[(size_t)row1 * 32 + p];
                    float t00 = cs0 * v00 - sn0 * v01;
                    float t01 = sn0 * v00 + cs0 * v01;
                    float t10 = cs1 * v10 - sn1 * v11;
                    float t11 = sn1 * v10 + cs1 * v11;
                    v00 = t00; v01 = t01; v10 = t10; v11 = t11;
                }
                const int b0r = row0 >> 11, s0 = row0 & (SS - 1);
                const int b1r = row1 >> 11, s1 = row1 & (SS - 1);
                size_t hb0 = ((size_t)(b0r * HH + h) * SS + s0) * 32 + (dk0 >> 1);
                size_t hb1 = ((size_t)(b1r * HH + h) * SS + s1) * 32 + (dk0 >> 1);
                if (seg == 0) {
                    uint32_t h0, l0, h1, l1;
                    split_pack_h(v00, v01, h0, l0);
                    split_pack_h(v10, v11, h1, l1);
                    ((uint32_t*)qhi)[hb0] = h0;  ((uint32_t*)qlo)[hb0] = l0;
                    ((uint32_t*)qhi)[hb1] = h1;  ((uint32_t*)qlo)[hb1] = l1;
                } else if (seg == 1) {
                    ((uint32_t*)kkp)[hb0] = pack_h(v00, v01);
                    ((uint32_t*)kkp)[hb1] = pack_h(v10, v11);
                } else {
                    ((uint32_t*)vvp)[hb0] = pack_h(v00, v01);
                    ((uint32_t*)vvp)[hb1] = pack_h(v10, v11);
                }
            }
        }
    }
}

// ======================= flash attention v3: fp16 2-pass ========================
// Q hi/lo (smem, static), K single (2 bufs), V single (2 bufs)
#define ROWB 144
#define TILEB 18432               // 128*144
#define AB_Q  0                   // Q hi at 0, Q lo at +TILEB
#define AB_K  (2*TILEB)           // 2 buffers
#define AB_V  (4*TILEB)           // 2 buffers
#define ATTN_SMEM_BYTES (6*TILEB) // 110592
#define CSC (0.125f * 1.44269504088896f)

__global__ __launch_bounds__(256)
void attn_mma3_kernel(const __half* __restrict__ qhi, const __half* __restrict__ qlo,
                      const __half* __restrict__ kk, const __half* __restrict__ vv,
                      __half* __restrict__ ohi, __half* __restrict__ olo)
{
    extern __shared__ uint32_t su[];
    const uint32_t sbase = smem_u32(su);

    const int tid = threadIdx.x;
    const int wid = tid >> 5;
    const int lid = tid & 31;
    const int r   = lid >> 2;
    const int c4  = lid & 3;
    const int i8  = lid & 7;
    const int m8  = lid >> 3;
    const int bh  = blockIdx.y;
    const int qt  = gridDim.x - 1 - blockIdx.x;
    const int q0  = qt * 128;

    const __half* qhp = qhi + (size_t)bh * SS * DK;
    const __half* qlp = qlo + (size_t)bh * SS * DK;
    const __half* khp = kk  + (size_t)bh * SS * DK;
    const __half* vhp = vv  + (size_t)bh * SS * DK;

    auto tile_cp = [&](uint32_t dstB, const __half* src, int row0g) {
        #pragma unroll
        for (int t = 0; t < 4; t++) {
            int id = tid + t * 256;
            int row = id >> 3, ch = id & 7;
            cp16(dstB + row * ROWB + ch * 16, src + (size_t)(row0g + row) * DK + ch * 8);
        }
    };
    auto prefetch_kv = [&](int kt, int buf) {
        int k0 = kt * 128;
        tile_cp(sbase + AB_K + buf * TILEB, khp, k0);
        tile_cp(sbase + AB_V + buf * TILEB, vhp, k0);
        CP_COMMIT();
    };

    tile_cp(sbase + AB_Q,         qhp, q0);
    tile_cp(sbase + AB_Q + TILEB, qlp, q0);
    prefetch_kv(0, 0);

    float mrow[2] = {-CUDART_INF_F, -CUDART_INF_F};
    float lrow[2] = {0.f, 0.f};
    float O[8][4];
    #pragma unroll
    for (int a = 0; a < 8; a++)
        #pragma unroll
        for (int b2 = 0; b2 < 4; b2++) O[a][b2] = 0.f;

    const uint32_t qa_lane = sbase + AB_Q +
        (uint32_t)(wid * 16 + i8 + ((m8 & 1) << 3)) * ROWB + ((m8 & 2) << 3);
    const uint32_t kb_lane = (uint32_t)(i8 + ((m8 & 2) << 2)) * ROWB + ((m8 & 1) << 4);
    const uint32_t va_lane = (uint32_t)(i8 + ((m8 & 1) << 3)) * ROWB + ((m8 & 2) << 3);

    for (int kt = 0; kt <= qt; kt++) {
        CP_WAIT0();
        __syncthreads();
        if (kt < qt) prefetch_kv(kt + 1, (kt + 1) & 1);

        const uint32_t kbuf = sbase + AB_K + (kt & 1) * TILEB;
        const uint32_t vbuf = sbase + AB_V + (kt & 1) * TILEB;

        // ---- S = Q K^T (2-pass: Qhi,Qlo vs K) ----
        float Sv[16][4];
        #pragma unroll
        for (int nt = 0; nt < 16; nt++)
            #pragma unroll
            for (int q = 0; q < 4; q++) Sv[nt][q] = 0.f;

        #pragma unroll
        for (int kc = 0; kc < 4; kc++) {
            uint32_t ah[4], al[4];
            LDSM4(ah, qa_lane + kc * 32);
            LDSM4(al, qa_lane + TILEB + kc * 32);
            #pragma unroll
            for (int ntp = 0; ntp < 8; ntp++) {
                uint32_t ka = kbuf + kb_lane + ntp * (16 * ROWB) + kc * 32;
                uint32_t bhv[4];
                LDSM4(bhv, ka);
                mma_f16(Sv[2*ntp],   ah, bhv[0], bhv[1]);
                mma_f16(Sv[2*ntp+1], ah, bhv[2], bhv[3]);
                mma_f16(Sv[2*ntp],   al, bhv[0], bhv[1]);
                mma_f16(Sv[2*ntp+1], al, bhv[2], bhv[3]);
            }
        }

        // scale into exp2 domain
        #pragma unroll
        for (int nt = 0; nt < 16; nt++)
            #pragma unroll
            for (int q = 0; q < 4; q++) Sv[nt][q] *= CSC;

        // ---- causal mask ----
        if (kt == qt) {
            int row0 = wid * 16 + r;
            int row1 = row0 + 8;
            #pragma unroll
            for (int nt = 0; nt < 16; nt++) {
                int col = nt * 8 + c4 * 2;
                if (col     > row0) Sv[nt][0] = -1e30f;
                if (col + 1 > row0) Sv[nt][1] = -1e30f;
                if (col     > row1) Sv[nt][2] = -1e30f;
                if (col + 1 > row1) Sv[nt][3] = -1e30f;
            }
        }

        // ---- online softmax ----
        #pragma unroll
        for (int hrow = 0; hrow < 2; hrow++) {
            float tm = -CUDART_INF_F;
            #pragma unroll
            for (int nt = 0; nt < 16; nt++) {
                tm = fmaxf(tm, Sv[nt][2*hrow]);
                tm = fmaxf(tm, Sv[nt][2*hrow + 1]);
            }
            tm = fmaxf(tm, __shfl_xor_sync(0xffffffffu, tm, 1));
            tm = fmaxf(tm, __shfl_xor_sync(0xffffffffu, tm, 2));
            float mn = fmaxf(mrow[hrow], tm);
            float alpha = exp2a(mrow[hrow] - mn);
            float ps = 0.f;
            #pragma unroll
            for (int nt = 0; nt < 16; nt++) {
                float p0 = exp2a(Sv[nt][2*hrow]     - mn);
                float p1 = exp2a(Sv[nt][2*hrow + 1] - mn);
                Sv[nt][2*hrow]     = p0;
                Sv[nt][2*hrow + 1] = p1;
                ps += p0 + p1;
            }
            ps += __shfl_xor_sync(0xffffffffu, ps, 1);
            ps += __shfl_xor_sync(0xffffffffu, ps, 2);
            lrow[hrow] = lrow[hrow] * alpha + ps;
            mrow[hrow] = mn;
            #pragma unroll
            for (int nt2 = 0; nt2 < 8; nt2++) {
                O[nt2][2*hrow]     *= alpha;
                O[nt2][2*hrow + 1] *= alpha;
            }
        }

        // ---- O += P V (2-pass: Phi,Plo vs V single) ----
        #pragma unroll
        for (int kc2 = 0; kc2 < 8; kc2++) {
            uint32_t pah[4], pal[4];
            split_pack_h(Sv[2*kc2][0],   Sv[2*kc2][1],   pah[0], pal[0]);
            split_pack_h(Sv[2*kc2][2],   Sv[2*kc2][3],   pah[1], pal[1]);
            split_pack_h(Sv[2*kc2+1][0], Sv[2*kc2+1][1], pah[2], pal[2]);
            split_pack_h(Sv[2*kc2+1][2], Sv[2*kc2+1][3], pah[3], pal[3]);
            uint32_t va0 = vbuf + va_lane + kc2 * (16 * ROWB);
            #pragma unroll
            for (int g = 0; g < 4; g++) {
                uint32_t bhv[4];
                LDSM4T(bhv, va0 + g * 32);
                mma_f16(O[2*g],   pah, bhv[0], bhv[1]);
                mma_f16(O[2*g+1], pah, bhv[2], bhv[3]);
                mma_f16(O[2*g],   pal, bhv[0], bhv[1]);
                mma_f16(O[2*g+1], pal, bhv[2], bhv[3]);
            }
        }
    }

    // ---- normalize + write fp16 hi/lo ----
    const int b = bh >> 4, h = bh & 15;
    const float inv0 = 1.0f / lrow[0];
    const float inv1 = 1.0f / lrow[1];
    const int row0g = q0 + wid * 16 + r;
    const int row1g = row0g + 8;
    #pragma unroll
    for (int nt2 = 0; nt2 < 8; nt2++) {
        int col = h * DK + nt2 * 8 + c4 * 2;
        float v00 = O[nt2][0] * inv0, v01 = O[nt2][1] * inv0;
        float v10 = O[nt2][2] * inv1, v11 = O[nt2][3] * inv1;
        uint32_t h0, l0, h1, l1;
        split_pack_h(v00, v01, h0, l0);
        split_pack_h(v10, v11, h1, l1);
        size_t o0 = ((size_t)(b * SS + row0g) * DD + col) >> 1;
        size_t o1 = ((size_t)(b * SS + row1g) * DD + col) >> 1;
        ((uint32_t*)ohi)[o0] = h0;
        ((uint32_t*)olo)[o0] = l0;
        ((uint32_t*)ohi)[o1] = h1;
        ((uint32_t*)olo)[o1] = l1;
    }
}

// ---------------- launch --------------------------------------------------------
extern "C" void kernel_launch(void* const* d_in, const int* in_sizes, int n_in,
                              void* d_out, int out_size)
{
    (void)in_sizes; (void)n_in; (void)out_size;
    const float* x  = (const float*)d_in[0];
    const float* Wq = (const float*)d_in[1];
    const float* Wk = (const float*)d_in[2];
    const float* Wv = (const float*)d_in[3];
    const float* Wo = (const float*)d_in[4];
    const int*   tp = (const int*)d_in[5];
    float* out = (float*)d_out;

    float *ct, *st;
    __half *xhi, *xlo, *wc, *wo, *qhi, *qlo, *kk, *vv, *abhi, *ablo;
    cudaGetSymbolAddress((void**)&ct, g_ct);
    cudaGetSymbolAddress((void**)&st, g_st);
    cudaGetSymbolAddress((void**)&xhi, g_xhi);   cudaGetSymbolAddress((void**)&xlo, g_xlo);
    cudaGetSymbolAddress((void**)&wc, g_wc);     cudaGetSymbolAddress((void**)&wo, g_wo);
    cudaGetSymbolAddress((void**)&qhi, g_qhi);   cudaGetSymbolAddress((void**)&qlo, g_qlo);
    cudaGetSymbolAddress((void**)&kk, g_kk);     cudaGetSymbolAddress((void**)&vv, g_vv);
    cudaGetSymbolAddress((void**)&abhi, g_abhi); cudaGetSymbolAddress((void**)&ablo, g_ablo);

    cudaFuncSetAttribute(gemm_mma5_kernel, cudaFuncAttributeMaxDynamicSharedMemorySize,
                         G5_SMEM_BYTES);
    cudaFuncSetAttribute(attn_mma3_kernel, cudaFuncAttributeMaxDynamicSharedMemorySize,
                         ATTN_SMEM_BYTES);

    const int ntot = NX4 + 4 * NW4;
    cvt_all_kernel<<<(ntot + 255)/256, 256>>>(x, Wq, Wk, Wv, Wo, xhi, xlo, wc, wo);
    rope_tab_kernel<<<(BB*SS*32 + 255)/256, 256>>>(tp, ct, st);

    // fused QKV projection
    gemm_mma5_kernel<<<dim3(24, (BB*SS)/128), 128, G5_SMEM_BYTES>>>(
        xhi, xlo, wc, ct, st, qhi, qlo, kk, vv, nullptr, 3);

    attn_mma3_kernel<<<dim3(SS / 128, BB * HH), 256, ATTN_SMEM_BYTES>>>(
        qhi, qlo, kk, vv, abhi, ablo);

    // output projection
    gemm_mma5_kernel<<<dim3(8, (BB*SS)/128), 128, G5_SMEM_BYTES>>>(
        abhi, ablo, wo, ct, st, nullptr, nullptr, nullptr, nullptr, out, 2);
}